// round 12
// baseline (speedup 1.0000x reference)
#include <cuda_runtime.h>
#include <cuda_fp16.h>
#include <math_constants.h>
#include <cstdint>

// Problem constants
#define B_    4
#define N_    2048
#define C_    1024
#define H_    16
#define D_    64
#define BHn   (B_ * H_)          // 64
#define MROWS (B_ * N_)          // 8192

// q pre-scale: 1/sqrt(64) * log2(e)  (softmax done in base-2)
#define QSCALE 0.18033688011112042f
#define ONE2   0x3C003C00u       // fp16x2 (1.0, 1.0)

// Scratch (static device arrays; no runtime allocation)
__device__ __half g_qh[(size_t)BHn * N_ * D_];    // [bh][n][d], pre-scaled
__device__ __half g_kh[(size_t)BHn * N_ * D_];    // [bh][n][d]
__device__ __half g_vh[(size_t)BHn * N_ * D_];    // [bh][d][n]  (TRANSPOSED)
__device__ __half g_ctxh[(size_t)MROWS * C_];     // [b*n][c]
__device__ __half g_xh[(size_t)MROWS * C_];       // x, fp16
__device__ __half g_wqkvh[(size_t)3 * C_ * C_];   // w_qkv^T  [3072][1024]
__device__ __half g_wprojh[(size_t)C_ * C_];      // w_proj^T [1024][1024]

// ---------------------------------------------------------------------------
// Helpers
// ---------------------------------------------------------------------------
__device__ __forceinline__ void mma_f16(float* d,
    unsigned a0, unsigned a1, unsigned a2, unsigned a3,
    unsigned b0, unsigned b1)
{
    asm volatile(
        "mma.sync.aligned.m16n8k16.row.col.f32.f16.f16.f32 "
        "{%0,%1,%2,%3}, {%4,%5,%6,%7}, {%8,%9}, {%0,%1,%2,%3};"
        : "+f"(d[0]), "+f"(d[1]), "+f"(d[2]), "+f"(d[3])
        : "r"(a0), "r"(a1), "r"(a2), "r"(a3), "r"(b0), "r"(b1));
}

__device__ __forceinline__ unsigned smem_u32(const void* p) {
    return (unsigned)__cvta_generic_to_shared(p);
}
__device__ __forceinline__ void cpa16(unsigned s, const void* g) {
    asm volatile("cp.async.cg.shared.global [%0], [%1], 16;" :: "r"(s), "l"(g));
}
#define CP_COMMIT() asm volatile("cp.async.commit_group;")
#define CP_WAIT2()  asm volatile("cp.async.wait_group 2;")

__device__ __forceinline__ void ldsm4(unsigned& r0, unsigned& r1,
                                      unsigned& r2, unsigned& r3, unsigned addr)
{
    asm volatile(
        "ldmatrix.sync.aligned.m8n8.x4.shared.b16 {%0,%1,%2,%3}, [%4];"
        : "=r"(r0), "=r"(r1), "=r"(r2), "=r"(r3) : "r"(addr));
}

__device__ __forceinline__ unsigned sw64(unsigned off)  { return off ^ ((off >> 3) & 0x30); }
__device__ __forceinline__ unsigned sw128(unsigned off) { return off ^ ((off >> 3) & 0x70); }

__device__ __forceinline__ unsigned packh2(float lo, float hi) {
    __half2 h = __floats2half2_rn(lo, hi);
    return *(unsigned*)&h;
}

__device__ __forceinline__ float ex2(float x) {
    float y;
    asm("ex2.approx.f32 %0, %1;" : "=f"(y) : "f"(x));
    return y;
}

__device__ __forceinline__ unsigned h2ex2(unsigned x) {
    unsigned y;
    asm("ex2.approx.f16x2 %0, %1;" : "=r"(y) : "r"(x));
    return y;
}

// ---------------------------------------------------------------------------
// Pre-pass kernels
// ---------------------------------------------------------------------------
__global__ void f2h_kernel(const float4* __restrict__ in,
                           __half2* __restrict__ out, int n4)
{
    int i = blockIdx.x * blockDim.x + threadIdx.x;
    if (i < n4) {
        float4 v = in[i];
        out[2 * i + 0] = __floats2half2_rn(v.x, v.y);
        out[2 * i + 1] = __floats2half2_rn(v.z, v.w);
    }
}

// in [K][Nn] fp32 -> outT [Nn][K] fp16
__global__ void transpose_h_kernel(const float* __restrict__ in,
                                   __half* __restrict__ outT, int K, int Nn)
{
    __shared__ float t[32][33];
    const int bx = blockIdx.x * 32;   // n
    const int by = blockIdx.y * 32;   // k
    const int x = threadIdx.x, y = threadIdx.y;
#pragma unroll
    for (int i = 0; i < 32; i += 8)
        t[y + i][x] = in[(size_t)(by + y + i) * Nn + bx + x];
    __syncthreads();
#pragma unroll
    for (int i = 0; i < 32; i += 8)
        outT[(size_t)(bx + y + i) * K + by + x] = __float2half_rn(t[x][y + i]);
}

// ---------------------------------------------------------------------------
// QKV GEMM: 64m x 128n CTA tile, warp tile 32x32, 3 CTAs/SM (24 warps).
// 256 threads, warp grid 2m x 4n. SW64 swizzle, 4-stage ring, lookahead 3.
// Scatters q/k/v (q scaled by QSCALE, v transposed).
// ---------------------------------------------------------------------------
#define Q_STAGE_BYTES (64 * 64 * 2 + 128 * 64 * 2 / 2)   // A 4KB + B 8KB = 12KB
#define Q_SMEM (4 * 12288)                               // 49152

__global__ __launch_bounds__(256, 3) void hgemm_qkv(
    const __half* __restrict__ A, const __half* __restrict__ Bt, int K)
{
    extern __shared__ char hsm[];
    const unsigned sbase0 = smem_u32(hsm);

    const int tid  = threadIdx.x;
    const int lane = tid & 31;
    const int wid  = tid >> 5;
    const int wm = (wid & 1) * 32;
    const int wn = (wid >> 1) * 32;
    const int r = lane >> 2;
    const int c = lane & 3;
    const int mBase = blockIdx.y * 64;
    const int nBase = blockIdx.x * 128;

    const int mat = lane >> 3, mrr = lane & 7;
    unsigned a_base[2], b_base[2];
#pragma unroll
    for (int mi = 0; mi < 2; mi++) {
        const int row = wm + mi * 16 + mrr + (mat & 1) * 8;
        a_base[mi] = row * 64 + (mat >> 1) * 16;
    }
#pragma unroll
    for (int p = 0; p < 2; p++) {
        const int row = wn + p * 16 + ((mat >> 1) & 1) * 8 + mrr;
        b_base[p] = 4096 + row * 64 + (mat & 1) * 16;
    }

    auto issue_tile = [&](int t) {
        const unsigned base = sbase0 + (t & 3) * 12288;
        const int kt = t * 32;
        {   // A: 64 rows x 4 chunks = 256
            const int row = tid >> 2, kc = tid & 3;
            cpa16(base + sw64(row * 64 + kc * 16),
                  &A[(size_t)(mBase + row) * K + kt + kc * 8]);
        }
#pragma unroll
        for (int i = 0; i < 2; i++) {   // B: 128 rows x 4 chunks = 512
            const int idx = tid + i * 256;
            const int row = idx >> 2, kc = idx & 3;
            cpa16(base + sw64(4096 + row * 64 + kc * 16),
                  &Bt[(size_t)(nBase + row) * K + kt + kc * 8]);
        }
    };

    float acc[2][4][4];
#pragma unroll
    for (int mi = 0; mi < 2; mi++)
#pragma unroll
        for (int ni = 0; ni < 4; ni++)
#pragma unroll
            for (int j = 0; j < 4; j++) acc[mi][ni][j] = 0.f;

    const int nT = K / 32;
    issue_tile(0); CP_COMMIT();
    issue_tile(1); CP_COMMIT();
    issue_tile(2); CP_COMMIT();

    for (int t = 0; t < nT; t++) {
        CP_WAIT2();
        __syncthreads();
        const unsigned sb = sbase0 + (t & 3) * 12288;

#pragma unroll
        for (int ks = 0; ks < 2; ks++) {
            unsigned a[2][4], bt2[2][4];
#pragma unroll
            for (int mi = 0; mi < 2; mi++)
                ldsm4(a[mi][0], a[mi][1], a[mi][2], a[mi][3],
                      sb + sw64(a_base[mi] + ks * 32));
#pragma unroll
            for (int p = 0; p < 2; p++)
                ldsm4(bt2[p][0], bt2[p][1], bt2[p][2], bt2[p][3],
                      sb + sw64(b_base[p] + ks * 32));
#pragma unroll
            for (int mi = 0; mi < 2; mi++)
#pragma unroll
                for (int ni = 0; ni < 4; ni++)
                    mma_f16(acc[mi][ni], a[mi][0], a[mi][1], a[mi][2], a[mi][3],
                            bt2[ni >> 1][(ni & 1) * 2],
                            bt2[ni >> 1][(ni & 1) * 2 + 1]);
        }

        if (t + 3 < nT) issue_tile(t + 3);
        CP_COMMIT();
    }

    // Epilogue: scatter q/k/v
#pragma unroll
    for (int mi = 0; mi < 2; mi++) {
        const int row0 = mBase + wm + mi * 16 + r;
#pragma unroll
        for (int ni = 0; ni < 4; ni++) {
            const int col = nBase + wn + ni * 8 + 2 * c;
#pragma unroll
            for (int hh = 0; hh < 2; hh++) {
                const int m = row0 + hh * 8;
                float v0 = acc[mi][ni][2 * hh + 0];
                float v1 = acc[mi][ni][2 * hh + 1];
                const int which = col >> 10;
                const int cc = col & 1023;
                const int h = cc >> 6;
                const int d = cc & 63;
                const int bb = m >> 11;
                const int nn = m & 2047;
                if (which == 0) {
                    __half2 w = __floats2half2_rn(v0 * QSCALE, v1 * QSCALE);
                    *(__half2*)&g_qh[(((size_t)(bb * H_ + h)) * N_ + nn) * D_ + d] = w;
                } else if (which == 1) {
                    __half2 w = __floats2half2_rn(v0, v1);
                    *(__half2*)&g_kh[(((size_t)(bb * H_ + h)) * N_ + nn) * D_ + d] = w;
                } else {
                    const size_t vb = ((size_t)(bb * H_ + h)) * D_;
                    g_vh[(vb + d) * N_ + nn]     = __float2half_rn(v0);
                    g_vh[(vb + d + 1) * N_ + nn] = __float2half_rn(v1);
                }
            }
        }
    }
}

// ---------------------------------------------------------------------------
// Proj GEMM (R7/R10 proven config): 128x128 CTA tile, warp 64x32, 2 CTAs/SM.
// ---------------------------------------------------------------------------
#define G_STAGE_BYTES (128 * 64 * 2)          // A 8KB + B 8KB
#define G_SMEM (4 * G_STAGE_BYTES)            // 65536

__global__ __launch_bounds__(256, 2) void hgemm_proj(
    const __half* __restrict__ Bt, const float* __restrict__ bias,
    float* __restrict__ Cout, int K)
{
    extern __shared__ char hsm[];
    const unsigned sbase0 = smem_u32(hsm);

    const int tid  = threadIdx.x;
    const int lane = tid & 31;
    const int wid  = tid >> 5;
    const int wm = (wid & 1) * 64;
    const int wn = (wid >> 1) * 32;
    const int r = lane >> 2;
    const int c = lane & 3;
    const int mBase = blockIdx.y * 128;
    const int nBase = blockIdx.x * 128;

    const __half* Aptr = (const __half*)g_ctxh;

    const int mat = lane >> 3, mrr = lane & 7;
    unsigned a_base[4], b_base[2];
#pragma unroll
    for (int mi = 0; mi < 4; mi++) {
        const int row = wm + mi * 16 + mrr + (mat & 1) * 8;
        a_base[mi] = row * 64 + (mat >> 1) * 16;
    }
#pragma unroll
    for (int p = 0; p < 2; p++) {
        const int row = wn + p * 16 + ((mat >> 1) & 1) * 8 + mrr;
        b_base[p] = 8192 + row * 64 + (mat & 1) * 16;
    }

    auto issue_tile = [&](int t) {
        const unsigned base = sbase0 + (t & 3) * G_STAGE_BYTES;
        const int kt = t * 32;
#pragma unroll
        for (int i = 0; i < 2; i++) {
            const int idx = tid + i * 256;
            const int row = idx >> 2, kc = idx & 3;
            cpa16(base + sw64(row * 64 + kc * 16),
                  &Aptr[(size_t)(mBase + row) * K + kt + kc * 8]);
        }
#pragma unroll
        for (int i = 0; i < 2; i++) {
            const int idx = tid + i * 256;
            const int row = idx >> 2, kc = idx & 3;
            cpa16(base + sw64(8192 + row * 64 + kc * 16),
                  &Bt[(size_t)(nBase + row) * K + kt + kc * 8]);
        }
    };

    float acc[4][4][4];
#pragma unroll
    for (int mi = 0; mi < 4; mi++)
#pragma unroll
        for (int ni = 0; ni < 4; ni++)
#pragma unroll
            for (int j = 0; j < 4; j++) acc[mi][ni][j] = 0.f;

    const int nT = K / 32;
    issue_tile(0); CP_COMMIT();
    issue_tile(1); CP_COMMIT();
    issue_tile(2); CP_COMMIT();

    for (int t = 0; t < nT; t++) {
        CP_WAIT2();
        __syncthreads();
        const unsigned sb = sbase0 + (t & 3) * G_STAGE_BYTES;

#pragma unroll
        for (int ks = 0; ks < 2; ks++) {
            unsigned a[4][4], bt2[2][4];
#pragma unroll
            for (int mi = 0; mi < 4; mi++)
                ldsm4(a[mi][0], a[mi][1], a[mi][2], a[mi][3],
                      sb + sw64(a_base[mi] + ks * 32));
#pragma unroll
            for (int p = 0; p < 2; p++)
                ldsm4(bt2[p][0], bt2[p][1], bt2[p][2], bt2[p][3],
                      sb + sw64(b_base[p] + ks * 32));
#pragma unroll
            for (int mi = 0; mi < 4; mi++)
#pragma unroll
                for (int ni = 0; ni < 4; ni++)
                    mma_f16(acc[mi][ni], a[mi][0], a[mi][1], a[mi][2], a[mi][3],
                            bt2[ni >> 1][(ni & 1) * 2],
                            bt2[ni >> 1][(ni & 1) * 2 + 1]);
        }

        if (t + 3 < nT) issue_tile(t + 3);
        CP_COMMIT();
    }

#pragma unroll
    for (int mi = 0; mi < 4; mi++) {
        const int row0 = mBase + wm + mi * 16 + r;
#pragma unroll
        for (int ni = 0; ni < 4; ni++) {
            const int col = nBase + wn + ni * 8 + 2 * c;
#pragma unroll
            for (int hh = 0; hh < 2; hh++) {
                const int m = row0 + hh * 8;
                float2 w = { acc[mi][ni][2 * hh + 0] + bias[col],
                             acc[mi][ni][2 * hh + 1] + bias[col + 1] };
                *(float2*)&Cout[(size_t)m * C_ + col] = w;
            }
        }
    }
}

// ---------------------------------------------------------------------------
// FP16 flash attention (R10-proven): 256 q rows/CTA, 8 warps x 32 q rows,
// 1 CTA/SM. K tile [64 keys][128B], V^T [64 d][128B], SW128, 4-stage ring.
// Base-2 softmax, fp16x2 exp, l via ones-column MMA.
// ---------------------------------------------------------------------------
#define A_STAGE_BYTES (64 * 128 * 2)           // K 8KB + V 8KB
#define ATTN_SMEM (4 * A_STAGE_BYTES)          // 65536

__global__ __launch_bounds__(256, 1) void hattn()
{
    extern __shared__ char asmm[];
    const unsigned sbase0 = smem_u32(asmm);

    const int bh = blockIdx.y;
    const int q0 = blockIdx.x * 256;
    const int tid = threadIdx.x;
    const int lane = tid & 31;
    const int wid = tid >> 5;
    const int r = lane >> 2;
    const int c = lane & 3;
    const int qw = wid * 32;

    const __half* Kg = g_kh + (size_t)bh * N_ * D_;
    const __half* Vt = g_vh + (size_t)bh * D_ * N_;   // [d][n]

    const int mat = lane >> 3, mrr = lane & 7;
    unsigned kb_base[4], vb_base[4];
#pragma unroll
    for (int p = 0; p < 4; p++) {
        const int row = p * 16 + ((mat >> 1) & 1) * 8 + mrr;
        kb_base[p] = row * 128 + (mat & 1) * 16;
        vb_base[p] = 8192 + row * 128 + (mat & 1) * 16;
    }

    auto issue_kv = [&](int t) {
        const unsigned base = sbase0 + (t & 3) * A_STAGE_BYTES;
        const int kt = t * 64;
#pragma unroll
        for (int i = 0; i < 4; i++) {
            const int idx = tid + i * 256;
            if (idx < 512) {                   // K tile: [key][d]
                const int row = idx >> 3, kc = idx & 7;
                cpa16(base + sw128(row * 128 + kc * 16),
                      &Kg[(size_t)(kt + row) * D_ + kc * 8]);
            } else {                           // V^T tile: [d][key]
                const int j = idx - 512;
                const int row = j >> 3, kc = j & 7;
                cpa16(base + sw128(8192 + row * 128 + kc * 16),
                      &Vt[(size_t)row * N_ + kt + kc * 8]);
            }
        }
    };

    // Q fragments -> registers (fp16, pre-scaled by QSCALE), 2 m-blocks
    unsigned qa[2][4][4];
#pragma unroll
    for (int mi = 0; mi < 2; mi++) {
        const __half* Qr0 = g_qh + (size_t)bh * N_ * D_
                          + (size_t)(q0 + qw + mi * 16 + r) * D_;
        const __half* Qr1 = Qr0 + 8 * D_;
#pragma unroll
        for (int ks = 0; ks < 4; ks++) {
            const int k0 = ks * 16 + 2 * c;
            qa[mi][ks][0] = *(const unsigned*)&Qr0[k0];
            qa[mi][ks][1] = *(const unsigned*)&Qr1[k0];
            qa[mi][ks][2] = *(const unsigned*)&Qr0[k0 + 8];
            qa[mi][ks][3] = *(const unsigned*)&Qr1[k0 + 8];
        }
    }

    float m0[2] = {-CUDART_INF_F, -CUDART_INF_F};
    float m1[2] = {-CUDART_INF_F, -CUDART_INF_F};
    float lacc[2][4] = {{0.f,0.f,0.f,0.f},{0.f,0.f,0.f,0.f}};
    float O[2][8][4];
#pragma unroll
    for (int mi = 0; mi < 2; mi++)
#pragma unroll
        for (int nb = 0; nb < 8; nb++)
#pragma unroll
            for (int j = 0; j < 4; j++) O[mi][nb][j] = 0.f;

    const int nT = N_ / 64;
    issue_kv(0); CP_COMMIT();
    issue_kv(1); CP_COMMIT();
    issue_kv(2); CP_COMMIT();

    for (int t = 0; t < nT; t++) {
        CP_WAIT2();
        __syncthreads();
        if (t + 3 < nT) issue_kv(t + 3);
        CP_COMMIT();

        const unsigned sb = sbase0 + (t & 3) * A_STAGE_BYTES;

        // S = Q @ K^T  (both m-blocks share each B-frag load)
        float s[2][8][4];
#pragma unroll
        for (int mi = 0; mi < 2; mi++)
#pragma unroll
            for (int nb = 0; nb < 8; nb++)
#pragma unroll
                for (int j = 0; j < 4; j++) s[mi][nb][j] = 0.f;

#pragma unroll
        for (int ks = 0; ks < 4; ks++) {
            unsigned bt2[4][4];
#pragma unroll
            for (int p = 0; p < 4; p++)
                ldsm4(bt2[p][0], bt2[p][1], bt2[p][2], bt2[p][3],
                      sb + sw128(kb_base[p] + ks * 32));
#pragma unroll
            for (int mi = 0; mi < 2; mi++)
#pragma unroll
                for (int nb = 0; nb < 8; nb++)
                    mma_f16(s[mi][nb],
                            qa[mi][ks][0], qa[mi][ks][1],
                            qa[mi][ks][2], qa[mi][ks][3],
                            bt2[nb >> 1][(nb & 1) * 2],
                            bt2[nb >> 1][(nb & 1) * 2 + 1]);
        }

        // Softmax per m-block; P frags via fp16x2 exp
        unsigned plo[2][8], phi[2][8];
#pragma unroll
        for (int mi = 0; mi < 2; mi++) {
            float mx0 = -CUDART_INF_F, mx1 = -CUDART_INF_F;
#pragma unroll
            for (int nb = 0; nb < 8; nb++) {
                mx0 = fmaxf(mx0, fmaxf(s[mi][nb][0], s[mi][nb][1]));
                mx1 = fmaxf(mx1, fmaxf(s[mi][nb][2], s[mi][nb][3]));
            }
            mx0 = fmaxf(mx0, __shfl_xor_sync(0xffffffffu, mx0, 1));
            mx0 = fmaxf(mx0, __shfl_xor_sync(0xffffffffu, mx0, 2));
            mx1 = fmaxf(mx1, __shfl_xor_sync(0xffffffffu, mx1, 1));
            mx1 = fmaxf(mx1, __shfl_xor_sync(0xffffffffu, mx1, 2));
            const float mn0 = fmaxf(m0[mi], mx0);
            const float mn1 = fmaxf(m1[mi], mx1);
            const float al0 = ex2(m0[mi] - mn0);
            const float al1 = ex2(m1[mi] - mn1);
            m0[mi] = mn0; m1[mi] = mn1;
#pragma unroll
            for (int nb = 0; nb < 8; nb++) {
                plo[mi][nb] = h2ex2(packh2(s[mi][nb][0] - mn0, s[mi][nb][1] - mn0));
                phi[mi][nb] = h2ex2(packh2(s[mi][nb][2] - mn1, s[mi][nb][3] - mn1));
            }
#pragma unroll
            for (int nb = 0; nb < 8; nb++) {
                O[mi][nb][0] *= al0; O[mi][nb][1] *= al0;
                O[mi][nb][2] *= al1; O[mi][nb][3] *= al1;
            }
            lacc[mi][0] *= al0; lacc[mi][1] *= al0;
            lacc[mi][2] *= al1; lacc[mi][3] *= al1;
        }

        // O += P @ V ; l += P @ ones  (V frags shared across m-blocks)
#pragma unroll
        for (int ks = 0; ks < 4; ks++) {
            unsigned vt2[4][4];
#pragma unroll
            for (int p = 0; p < 4; p++)
                ldsm4(vt2[p][0], vt2[p][1], vt2[p][2], vt2[p][3],
                      sb + sw128(vb_base[p] + ks * 32));
#pragma unroll
            for (int mi = 0; mi < 2; mi++) {
                const unsigned a0 = plo[mi][2 * ks];
                const unsigned a1 = phi[mi][2 * ks];
                const unsigned a2 = plo[mi][2 * ks + 1];
                const unsigned a3 = phi[mi][2 * ks + 1];
                mma_f16(lacc[mi], a0, a1, a2, a3, ONE2, ONE2);
#pragma unroll
                for (int nb = 0; nb < 8; nb++)
                    mma_f16(O[mi][nb], a0, a1, a2, a3,
                            vt2[nb >> 1][(nb & 1) * 2],
                            vt2[nb >> 1][(nb & 1) * 2 + 1]);
            }
        }
    }

    // Normalize + write ctx fp16 [b*n][h*64+d]
    const int bb = bh >> 4;
    const int h = bh & 15;
#pragma unroll
    for (int mi = 0; mi < 2; mi++) {
        const float inv0 = 1.f / lacc[mi][0];
        const float inv1 = 1.f / lacc[mi][2];
        const int row0 = q0 + qw + mi * 16 + r;
        const int row1 = row0 + 8;
#pragma unroll
        for (int nb = 0; nb < 8; nb++) {
            const int col = h * 64 + nb * 8 + 2 * c;
            __half2 w0 = __floats2half2_rn(O[mi][nb][0] * inv0, O[mi][nb][1] * inv0);
            __half2 w1 = __floats2half2_rn(O[mi][nb][2] * inv1, O[mi][nb][3] * inv1);
            *(__half2*)&g_ctxh[((size_t)(bb * N_ + row0)) * C_ + col] = w0;
            *(__half2*)&g_ctxh[((size_t)(bb * N_ + row1)) * C_ + col] = w1;
        }
    }
}

// ---------------------------------------------------------------------------
extern "C" void kernel_launch(void* const* d_in, const int* in_sizes, int n_in,
                              void* d_out, int out_size)
{
    const float* x      = (const float*)d_in[0];
    const float* w_qkv  = (const float*)d_in[1];
    const float* w_proj = (const float*)d_in[2];
    const float* b_proj = (const float*)d_in[3];
    float* out = (float*)d_out;

    cudaFuncSetAttribute(hgemm_qkv,
                         cudaFuncAttributeMaxDynamicSharedMemorySize, Q_SMEM);
    cudaFuncSetAttribute(hgemm_proj,
                         cudaFuncAttributeMaxDynamicSharedMemorySize, G_SMEM);
    cudaFuncSetAttribute(hattn,
                         cudaFuncAttributeMaxDynamicSharedMemorySize, ATTN_SMEM);

    __half* xh; __half* wqT; __half* wpT;
    cudaGetSymbolAddress((void**)&xh, g_xh);
    cudaGetSymbolAddress((void**)&wqT, g_wqkvh);
    cudaGetSymbolAddress((void**)&wpT, g_wprojh);

    // 0) pre-pass: x -> fp16; weights -> transposed fp16
    {
        int n4x = MROWS * C_ / 4;
        f2h_kernel<<<n4x / 256, 256>>>((const float4*)x, (__half2*)xh, n4x);
        dim3 tb(32, 8);
        transpose_h_kernel<<<dim3(3 * C_ / 32, C_ / 32), tb>>>(w_qkv, wqT, C_, 3 * C_);
        transpose_h_kernel<<<dim3(C_ / 32, C_ / 32), tb>>>(w_proj, wpT, C_, C_);
    }

    // 1) QKV projection: 64x128 tiles, 3 CTAs/SM
    hgemm_qkv<<<dim3(3 * C_ / 128, MROWS / 64), 256, Q_SMEM>>>(xh, wqT, C_);

    // 2) Attention: 8 q-tiles (256 rows) x 64 heads
    hattn<<<dim3(N_ / 256, BHn), 256, ATTN_SMEM>>>();

    // 3) Output projection + bias (fp32 out)
    hgemm_proj<<<dim3(C_ / 128, MROWS / 128), 256, G_SMEM>>>(
        wpT, b_proj, out, C_);
}

// round 13
// speedup vs baseline: 1.0521x; 1.0521x over previous
#include <cuda_runtime.h>
#include <cuda_fp16.h>
#include <math_constants.h>
#include <cstdint>

// Problem constants
#define B_    4
#define N_    2048
#define C_    1024
#define H_    16
#define D_    64
#define BHn   (B_ * H_)          // 64
#define MROWS (B_ * N_)          // 8192

// q pre-scale: 1/sqrt(64) * log2(e)  (softmax done in base-2)
#define QSCALE 0.18033688011112042f
#define ONE2   0x3C003C00u       // fp16x2 (1.0, 1.0)

// Scratch (static device arrays; no runtime allocation)
__device__ __half g_qh[(size_t)BHn * N_ * D_];    // [bh][n][d], pre-scaled
__device__ __half g_kh[(size_t)BHn * N_ * D_];    // [bh][n][d]
__device__ __half g_vh[(size_t)BHn * N_ * D_];    // [bh][d][n]  (TRANSPOSED)
__device__ __half g_ctxh[(size_t)MROWS * C_];     // [b*n][c]
__device__ __half g_xh[(size_t)MROWS * C_];       // x, fp16
__device__ __half g_wqkvh[(size_t)3 * C_ * C_];   // w_qkv^T  [3072][1024]
__device__ __half g_wprojh[(size_t)C_ * C_];      // w_proj^T [1024][1024]

// ---------------------------------------------------------------------------
// Helpers
// ---------------------------------------------------------------------------
__device__ __forceinline__ void mma_f16(float* d,
    unsigned a0, unsigned a1, unsigned a2, unsigned a3,
    unsigned b0, unsigned b1)
{
    asm volatile(
        "mma.sync.aligned.m16n8k16.row.col.f32.f16.f16.f32 "
        "{%0,%1,%2,%3}, {%4,%5,%6,%7}, {%8,%9}, {%0,%1,%2,%3};"
        : "+f"(d[0]), "+f"(d[1]), "+f"(d[2]), "+f"(d[3])
        : "r"(a0), "r"(a1), "r"(a2), "r"(a3), "r"(b0), "r"(b1));
}

__device__ __forceinline__ unsigned smem_u32(const void* p) {
    return (unsigned)__cvta_generic_to_shared(p);
}
__device__ __forceinline__ void cpa16(unsigned s, const void* g) {
    asm volatile("cp.async.cg.shared.global [%0], [%1], 16;" :: "r"(s), "l"(g));
}
#define CP_COMMIT() asm volatile("cp.async.commit_group;")
#define CP_WAIT2()  asm volatile("cp.async.wait_group 2;")

__device__ __forceinline__ void ldsm4(unsigned& r0, unsigned& r1,
                                      unsigned& r2, unsigned& r3, unsigned addr)
{
    asm volatile(
        "ldmatrix.sync.aligned.m8n8.x4.shared.b16 {%0,%1,%2,%3}, [%4];"
        : "=r"(r0), "=r"(r1), "=r"(r2), "=r"(r3) : "r"(addr));
}

__device__ __forceinline__ unsigned sw64(unsigned off)  { return off ^ ((off >> 3) & 0x30); }
__device__ __forceinline__ unsigned sw128(unsigned off) { return off ^ ((off >> 3) & 0x70); }

__device__ __forceinline__ unsigned packh2(float lo, float hi) {
    __half2 h = __floats2half2_rn(lo, hi);
    return *(unsigned*)&h;
}

__device__ __forceinline__ float ex2(float x) {
    float y;
    asm("ex2.approx.f32 %0, %1;" : "=f"(y) : "f"(x));
    return y;
}

__device__ __forceinline__ unsigned h2ex2(unsigned x) {
    unsigned y;
    asm("ex2.approx.f16x2 %0, %1;" : "=r"(y) : "r"(x));
    return y;
}

// ---------------------------------------------------------------------------
// Fused pre-pass: one kernel covers
//   blocks [0, 8192)        : x fp32 -> fp16           (256 float4 / block)
//   blocks [8192, 11264)    : w_qkv  transpose->fp16   ((32,8)-style tile)
//   blocks [11264, 12288)   : w_proj transpose->fp16
// All jobs use 256-thread blocks.
// ---------------------------------------------------------------------------
#define PRE_F2H_BLOCKS   (MROWS * C_ / 4 / 256)          // 8192
#define PRE_WQKV_BLOCKS  ((3 * C_ / 32) * (C_ / 32))     // 3072
#define PRE_WPROJ_BLOCKS ((C_ / 32) * (C_ / 32))         // 1024
#define PRE_BLOCKS (PRE_F2H_BLOCKS + PRE_WQKV_BLOCKS + PRE_WPROJ_BLOCKS)

__global__ __launch_bounds__(256) void prepass_kernel(
    const float4* __restrict__ x4, __half2* __restrict__ xh2,
    const float* __restrict__ wqkv, __half* __restrict__ wqT,
    const float* __restrict__ wproj, __half* __restrict__ wpT)
{
    __shared__ float t[32][33];
    const int b = blockIdx.x;
    const int tid = threadIdx.x;

    if (b < PRE_F2H_BLOCKS) {
        const int i = b * 256 + tid;
        float4 v = x4[i];
        xh2[2 * i + 0] = __floats2half2_rn(v.x, v.y);
        xh2[2 * i + 1] = __floats2half2_rn(v.z, v.w);
        return;
    }

    // Transpose job: in [K][Nn] fp32 -> outT [Nn][K] fp16
    const float* in;
    __half* outT;
    int Nn, bx, by;
    if (b < PRE_F2H_BLOCKS + PRE_WQKV_BLOCKS) {
        const int id = b - PRE_F2H_BLOCKS;
        in = wqkv; outT = wqT; Nn = 3 * C_;
        bx = (id % (3 * C_ / 32)) * 32;
        by = (id / (3 * C_ / 32)) * 32;
    } else {
        const int id = b - PRE_F2H_BLOCKS - PRE_WQKV_BLOCKS;
        in = wproj; outT = wpT; Nn = C_;
        bx = (id % (C_ / 32)) * 32;
        by = (id / (C_ / 32)) * 32;
    }
    const int x = tid & 31, y = tid >> 5;    // (32, 8)
#pragma unroll
    for (int i = 0; i < 32; i += 8)
        t[y + i][x] = in[(size_t)(by + y + i) * Nn + bx + x];
    __syncthreads();
#pragma unroll
    for (int i = 0; i < 32; i += 8)
        outT[(size_t)(bx + y + i) * C_ + by + x] = __float2half_rn(t[x][y + i]);
}

// ---------------------------------------------------------------------------
// FP16 GEMM via mma.sync m16n8k16 + ldmatrix.  (R7/R10 proven — 152.9us)
// D[m][n] = sum_k A[m][k] * Bt[n][k]. CTA tile 128x128, k-chunk 32 halves.
// 256 threads, warp grid 2m x 4n, warp tile 64x32. SW64 swizzle on 64B rows.
// 4-stage cp.async ring, lookahead 3.
// MODE 0: scatter q/k/v (q scaled by QSCALE, v transposed). MODE 1: +bias.
// ---------------------------------------------------------------------------
#define G_STAGE_BYTES (128 * 64 * 2)          // A 8KB + B 8KB
#define G_SMEM (4 * G_STAGE_BYTES)            // 65536

template <int MODE>
__global__ __launch_bounds__(256, 2) void hgemm(
    const __half* __restrict__ A, const __half* __restrict__ Bt,
    const float* __restrict__ bias, float* __restrict__ Cout, int K)
{
    extern __shared__ char hsm[];
    const unsigned sbase0 = smem_u32(hsm);

    const int tid  = threadIdx.x;
    const int lane = tid & 31;
    const int wid  = tid >> 5;
    const int wm = (wid & 1) * 64;
    const int wn = (wid >> 1) * 32;
    const int r = lane >> 2;
    const int c = lane & 3;
    const int mBase = blockIdx.y * 128;
    const int nBase = blockIdx.x * 128;

    const __half* Aptr = (MODE == 1) ? (const __half*)g_ctxh : A;

    const int mat = lane >> 3, mrr = lane & 7;
    unsigned a_base[4], b_base[2];
#pragma unroll
    for (int mi = 0; mi < 4; mi++) {
        const int row = wm + mi * 16 + mrr + (mat & 1) * 8;
        a_base[mi] = row * 64 + (mat >> 1) * 16;
    }
#pragma unroll
    for (int p = 0; p < 2; p++) {
        const int row = wn + p * 16 + ((mat >> 1) & 1) * 8 + mrr;
        b_base[p] = 8192 + row * 64 + (mat & 1) * 16;
    }

    auto issue_tile = [&](int t) {
        const unsigned base = sbase0 + (t & 3) * G_STAGE_BYTES;
        const int kt = t * 32;
#pragma unroll
        for (int i = 0; i < 2; i++) {
            const int idx = tid + i * 256;
            const int row = idx >> 2, kc = idx & 3;
            cpa16(base + sw64(row * 64 + kc * 16),
                  &Aptr[(size_t)(mBase + row) * K + kt + kc * 8]);
        }
#pragma unroll
        for (int i = 0; i < 2; i++) {
            const int idx = tid + i * 256;
            const int row = idx >> 2, kc = idx & 3;
            cpa16(base + sw64(8192 + row * 64 + kc * 16),
                  &Bt[(size_t)(nBase + row) * K + kt + kc * 8]);
        }
    };

    float acc[4][4][4];
#pragma unroll
    for (int mi = 0; mi < 4; mi++)
#pragma unroll
        for (int ni = 0; ni < 4; ni++)
#pragma unroll
            for (int j = 0; j < 4; j++) acc[mi][ni][j] = 0.f;

    const int nT = K / 32;
    issue_tile(0); CP_COMMIT();
    issue_tile(1); CP_COMMIT();
    issue_tile(2); CP_COMMIT();

    for (int t = 0; t < nT; t++) {
        CP_WAIT2();
        __syncthreads();
        const unsigned sb = sbase0 + (t & 3) * G_STAGE_BYTES;

#pragma unroll
        for (int ks = 0; ks < 2; ks++) {
            unsigned a[4][4], bt2[2][4];
#pragma unroll
            for (int mi = 0; mi < 4; mi++)
                ldsm4(a[mi][0], a[mi][1], a[mi][2], a[mi][3],
                      sb + sw64(a_base[mi] + ks * 32));
#pragma unroll
            for (int p = 0; p < 2; p++)
                ldsm4(bt2[p][0], bt2[p][1], bt2[p][2], bt2[p][3],
                      sb + sw64(b_base[p] + ks * 32));
#pragma unroll
            for (int mi = 0; mi < 4; mi++)
#pragma unroll
                for (int ni = 0; ni < 4; ni++)
                    mma_f16(acc[mi][ni], a[mi][0], a[mi][1], a[mi][2], a[mi][3],
                            bt2[ni >> 1][(ni & 1) * 2],
                            bt2[ni >> 1][(ni & 1) * 2 + 1]);
        }

        if (t + 3 < nT) issue_tile(t + 3);
        CP_COMMIT();
    }

    // Epilogue
#pragma unroll
    for (int mi = 0; mi < 4; mi++) {
        const int row0 = mBase + wm + mi * 16 + r;
#pragma unroll
        for (int ni = 0; ni < 4; ni++) {
            const int col = nBase + wn + ni * 8 + 2 * c;
#pragma unroll
            for (int hh = 0; hh < 2; hh++) {
                const int m = row0 + hh * 8;
                float v0 = acc[mi][ni][2 * hh + 0];
                float v1 = acc[mi][ni][2 * hh + 1];
                if (MODE == 0) {
                    const int which = col >> 10;
                    const int cc = col & 1023;
                    const int h = cc >> 6;
                    const int d = cc & 63;
                    const int bb = m >> 11;
                    const int nn = m & 2047;
                    if (which == 0) {
                        __half2 w = __floats2half2_rn(v0 * QSCALE, v1 * QSCALE);
                        *(__half2*)&g_qh[(((size_t)(bb * H_ + h)) * N_ + nn) * D_ + d] = w;
                    } else if (which == 1) {
                        __half2 w = __floats2half2_rn(v0, v1);
                        *(__half2*)&g_kh[(((size_t)(bb * H_ + h)) * N_ + nn) * D_ + d] = w;
                    } else {
                        const size_t vb = ((size_t)(bb * H_ + h)) * D_;
                        g_vh[(vb + d) * N_ + nn]     = __float2half_rn(v0);
                        g_vh[(vb + d + 1) * N_ + nn] = __float2half_rn(v1);
                    }
                } else {
                    float2 w = { v0 + bias[col], v1 + bias[col + 1] };
                    *(float2*)&Cout[(size_t)m * C_ + col] = w;
                }
            }
        }
    }
}

// ---------------------------------------------------------------------------
// FP16 flash attention (R10-proven): 256 q rows/CTA, 8 warps x 32 q rows,
// 1 CTA/SM. K tile [64 keys][128B], V^T [64 d][128B], SW128, 4-stage ring.
// Base-2 softmax, fp16x2 exp, l via ones-column MMA.
// ---------------------------------------------------------------------------
#define A_STAGE_BYTES (64 * 128 * 2)           // K 8KB + V 8KB
#define ATTN_SMEM (4 * A_STAGE_BYTES)          // 65536

__global__ __launch_bounds__(256, 1) void hattn()
{
    extern __shared__ char asmm[];
    const unsigned sbase0 = smem_u32(asmm);

    const int bh = blockIdx.y;
    const int q0 = blockIdx.x * 256;
    const int tid = threadIdx.x;
    const int lane = tid & 31;
    const int wid = tid >> 5;
    const int r = lane >> 2;
    const int c = lane & 3;
    const int qw = wid * 32;

    const __half* Kg = g_kh + (size_t)bh * N_ * D_;
    const __half* Vt = g_vh + (size_t)bh * D_ * N_;   // [d][n]

    const int mat = lane >> 3, mrr = lane & 7;
    unsigned kb_base[4], vb_base[4];
#pragma unroll
    for (int p = 0; p < 4; p++) {
        const int row = p * 16 + ((mat >> 1) & 1) * 8 + mrr;
        kb_base[p] = row * 128 + (mat & 1) * 16;
        vb_base[p] = 8192 + row * 128 + (mat & 1) * 16;
    }

    auto issue_kv = [&](int t) {
        const unsigned base = sbase0 + (t & 3) * A_STAGE_BYTES;
        const int kt = t * 64;
#pragma unroll
        for (int i = 0; i < 4; i++) {
            const int idx = tid + i * 256;
            if (idx < 512) {                   // K tile: [key][d]
                const int row = idx >> 3, kc = idx & 7;
                cpa16(base + sw128(row * 128 + kc * 16),
                      &Kg[(size_t)(kt + row) * D_ + kc * 8]);
            } else {                           // V^T tile: [d][key]
                const int j = idx - 512;
                const int row = j >> 3, kc = j & 7;
                cpa16(base + sw128(8192 + row * 128 + kc * 16),
                      &Vt[(size_t)row * N_ + kt + kc * 8]);
            }
        }
    };

    // Q fragments -> registers (fp16, pre-scaled by QSCALE), 2 m-blocks
    unsigned qa[2][4][4];
#pragma unroll
    for (int mi = 0; mi < 2; mi++) {
        const __half* Qr0 = g_qh + (size_t)bh * N_ * D_
                          + (size_t)(q0 + qw + mi * 16 + r) * D_;
        const __half* Qr1 = Qr0 + 8 * D_;
#pragma unroll
        for (int ks = 0; ks < 4; ks++) {
            const int k0 = ks * 16 + 2 * c;
            qa[mi][ks][0] = *(const unsigned*)&Qr0[k0];
            qa[mi][ks][1] = *(const unsigned*)&Qr1[k0];
            qa[mi][ks][2] = *(const unsigned*)&Qr0[k0 + 8];
            qa[mi][ks][3] = *(const unsigned*)&Qr1[k0 + 8];
        }
    }

    float m0[2] = {-CUDART_INF_F, -CUDART_INF_F};
    float m1[2] = {-CUDART_INF_F, -CUDART_INF_F};
    float lacc[2][4] = {{0.f,0.f,0.f,0.f},{0.f,0.f,0.f,0.f}};
    float O[2][8][4];
#pragma unroll
    for (int mi = 0; mi < 2; mi++)
#pragma unroll
        for (int nb = 0; nb < 8; nb++)
#pragma unroll
            for (int j = 0; j < 4; j++) O[mi][nb][j] = 0.f;

    const int nT = N_ / 64;
    issue_kv(0); CP_COMMIT();
    issue_kv(1); CP_COMMIT();
    issue_kv(2); CP_COMMIT();

    for (int t = 0; t < nT; t++) {
        CP_WAIT2();
        __syncthreads();
        if (t + 3 < nT) issue_kv(t + 3);
        CP_COMMIT();

        const unsigned sb = sbase0 + (t & 3) * A_STAGE_BYTES;

        // S = Q @ K^T  (both m-blocks share each B-frag load)
        float s[2][8][4];
#pragma unroll
        for (int mi = 0; mi < 2; mi++)
#pragma unroll
            for (int nb = 0; nb < 8; nb++)
#pragma unroll
                for (int j = 0; j < 4; j++) s[mi][nb][j] = 0.f;

#pragma unroll
        for (int ks = 0; ks < 4; ks++) {
            unsigned bt2[4][4];
#pragma unroll
            for (int p = 0; p < 4; p++)
                ldsm4(bt2[p][0], bt2[p][1], bt2[p][2], bt2[p][3],
                      sb + sw128(kb_base[p] + ks * 32));
#pragma unroll
            for (int mi = 0; mi < 2; mi++)
#pragma unroll
                for (int nb = 0; nb < 8; nb++)
                    mma_f16(s[mi][nb],
                            qa[mi][ks][0], qa[mi][ks][1],
                            qa[mi][ks][2], qa[mi][ks][3],
                            bt2[nb >> 1][(nb & 1) * 2],
                            bt2[nb >> 1][(nb & 1) * 2 + 1]);
        }

        // Softmax per m-block; P frags via fp16x2 exp
        unsigned plo[2][8], phi[2][8];
#pragma unroll
        for (int mi = 0; mi < 2; mi++) {
            float mx0 = -CUDART_INF_F, mx1 = -CUDART_INF_F;
#pragma unroll
            for (int nb = 0; nb < 8; nb++) {
                mx0 = fmaxf(mx0, fmaxf(s[mi][nb][0], s[mi][nb][1]));
                mx1 = fmaxf(mx1, fmaxf(s[mi][nb][2], s[mi][nb][3]));
            }
            mx0 = fmaxf(mx0, __shfl_xor_sync(0xffffffffu, mx0, 1));
            mx0 = fmaxf(mx0, __shfl_xor_sync(0xffffffffu, mx0, 2));
            mx1 = fmaxf(mx1, __shfl_xor_sync(0xffffffffu, mx1, 1));
            mx1 = fmaxf(mx1, __shfl_xor_sync(0xffffffffu, mx1, 2));
            const float mn0 = fmaxf(m0[mi], mx0);
            const float mn1 = fmaxf(m1[mi], mx1);
            const float al0 = ex2(m0[mi] - mn0);
            const float al1 = ex2(m1[mi] - mn1);
            m0[mi] = mn0; m1[mi] = mn1;
#pragma unroll
            for (int nb = 0; nb < 8; nb++) {
                plo[mi][nb] = h2ex2(packh2(s[mi][nb][0] - mn0, s[mi][nb][1] - mn0));
                phi[mi][nb] = h2ex2(packh2(s[mi][nb][2] - mn1, s[mi][nb][3] - mn1));
            }
#pragma unroll
            for (int nb = 0; nb < 8; nb++) {
                O[mi][nb][0] *= al0; O[mi][nb][1] *= al0;
                O[mi][nb][2] *= al1; O[mi][nb][3] *= al1;
            }
            lacc[mi][0] *= al0; lacc[mi][1] *= al0;
            lacc[mi][2] *= al1; lacc[mi][3] *= al1;
        }

        // O += P @ V ; l += P @ ones  (V frags shared across m-blocks)
#pragma unroll
        for (int ks = 0; ks < 4; ks++) {
            unsigned vt2[4][4];
#pragma unroll
            for (int p = 0; p < 4; p++)
                ldsm4(vt2[p][0], vt2[p][1], vt2[p][2], vt2[p][3],
                      sb + sw128(vb_base[p] + ks * 32));
#pragma unroll
            for (int mi = 0; mi < 2; mi++) {
                const unsigned a0 = plo[mi][2 * ks];
                const unsigned a1 = phi[mi][2 * ks];
                const unsigned a2 = plo[mi][2 * ks + 1];
                const unsigned a3 = phi[mi][2 * ks + 1];
                mma_f16(lacc[mi], a0, a1, a2, a3, ONE2, ONE2);
#pragma unroll
                for (int nb = 0; nb < 8; nb++)
                    mma_f16(O[mi][nb], a0, a1, a2, a3,
                            vt2[nb >> 1][(nb & 1) * 2],
                            vt2[nb >> 1][(nb & 1) * 2 + 1]);
            }
        }
    }

    // Normalize + write ctx fp16 [b*n][h*64+d]
    const int bb = bh >> 4;
    const int h = bh & 15;
#pragma unroll
    for (int mi = 0; mi < 2; mi++) {
        const float inv0 = 1.f / lacc[mi][0];
        const float inv1 = 1.f / lacc[mi][2];
        const int row0 = q0 + qw + mi * 16 + r;
        const int row1 = row0 + 8;
#pragma unroll
        for (int nb = 0; nb < 8; nb++) {
            const int col = h * 64 + nb * 8 + 2 * c;
            __half2 w0 = __floats2half2_rn(O[mi][nb][0] * inv0, O[mi][nb][1] * inv0);
            __half2 w1 = __floats2half2_rn(O[mi][nb][2] * inv1, O[mi][nb][3] * inv1);
            *(__half2*)&g_ctxh[((size_t)(bb * N_ + row0)) * C_ + col] = w0;
            *(__half2*)&g_ctxh[((size_t)(bb * N_ + row1)) * C_ + col] = w1;
        }
    }
}

// ---------------------------------------------------------------------------
extern "C" void kernel_launch(void* const* d_in, const int* in_sizes, int n_in,
                              void* d_out, int out_size)
{
    const float* x      = (const float*)d_in[0];
    const float* w_qkv  = (const float*)d_in[1];
    const float* w_proj = (const float*)d_in[2];
    const float* b_proj = (const float*)d_in[3];
    float* out = (float*)d_out;

    cudaFuncSetAttribute(hgemm<0>,
                         cudaFuncAttributeMaxDynamicSharedMemorySize, G_SMEM);
    cudaFuncSetAttribute(hgemm<1>,
                         cudaFuncAttributeMaxDynamicSharedMemorySize, G_SMEM);
    cudaFuncSetAttribute(hattn,
                         cudaFuncAttributeMaxDynamicSharedMemorySize, ATTN_SMEM);

    __half* xh; __half* wqT; __half* wpT;
    cudaGetSymbolAddress((void**)&xh, g_xh);
    cudaGetSymbolAddress((void**)&wqT, g_wqkvh);
    cudaGetSymbolAddress((void**)&wpT, g_wprojh);

    // 0) fused pre-pass: x -> fp16; weights -> transposed fp16 (one launch)
    prepass_kernel<<<PRE_BLOCKS, 256>>>(
        (const float4*)x, (__half2*)xh, w_qkv, wqT, w_proj, wpT);

    // 1) QKV projection: [8192,1024] @ w_qkv -> q/k/v (v transposed)
    hgemm<0><<<dim3(3 * C_ / 128, MROWS / 128), 256, G_SMEM>>>(
        xh, wqT, nullptr, nullptr, C_);

    // 2) Attention: 8 q-tiles (256 rows) x 64 heads
    hattn<<<dim3(N_ / 256, BHn), 256, ATTN_SMEM>>>();

    // 3) Output projection + bias (fp32 out)
    hgemm<1><<<dim3(C_ / 128, MROWS / 128), 256, G_SMEM>>>(
        nullptr, wpT, b_proj, out, C_);
}